// round 2
// baseline (speedup 1.0000x reference)
#include <cuda_runtime.h>
#include <cuda_bf16.h>

// Problem dims (fixed)
#define B    32
#define T    64
#define DIN  10000
#define H    200
#define NCLS 2
#define M_TOT (B * T)          // 2048

// Scratch (device globals: no allocation allowed)
__device__ float g_pre[M_TOT * H];
__device__ float g_h[M_TOT * H];

// ---------------------------------------------------------------------------
// GEMM: C[m,n] = sum_k A[m,k] * W[n,k] + b1[n] + b2[n]
// A: [M,K] row-major, W: [N,K] row-major. 64x64 tile, BK=16, 4x4 per thread.
// K is a multiple of 4 (10000 / 200), so each float4 k-load is either fully
// in range or fully out -> single predicate, zero-fill both tiles.
// ---------------------------------------------------------------------------
__global__ __launch_bounds__(256)
void gemm_abt_bias(const float* __restrict__ A,
                   const float* __restrict__ W,
                   const float* __restrict__ b1,
                   const float* __restrict__ b2,
                   float* __restrict__ C,
                   int M, int N, int K) {
    __shared__ float As[16][64];
    __shared__ float Ws[16][64];

    const int bm = blockIdx.y * 64;
    const int bn = blockIdx.x * 64;
    const int tid = threadIdx.x;
    const int tx = tid % 16;        // n micro-tile
    const int ty = tid / 16;        // m micro-tile

    // loader: each thread loads one float4 of A-tile and one of W-tile
    const int lm = tid / 4;         // 0..63 (row within tile)
    const int lk = (tid % 4) * 4;   // 0,4,8,12 (k within tile)

    float acc[4][4] = {};

    for (int k0 = 0; k0 < K; k0 += 16) {
        const int kbase = k0 + lk;
        const bool kok = (kbase < K);   // K%4==0 -> float4 fully valid iff this

        // A tile (M rows always in range: M=2048 divisible by 64)
        float4 av = make_float4(0.f, 0.f, 0.f, 0.f);
        if (kok) av = *(const float4*)&A[(size_t)(bm + lm) * K + kbase];
        As[lk + 0][lm] = av.x;
        As[lk + 1][lm] = av.y;
        As[lk + 2][lm] = av.z;
        As[lk + 3][lm] = av.w;

        // W tile (guard n < N; N=200 with 4 tiles of 64)
        float4 wv = make_float4(0.f, 0.f, 0.f, 0.f);
        int n = bn + lm;
        if (kok && n < N) wv = *(const float4*)&W[(size_t)n * K + kbase];
        Ws[lk + 0][lm] = wv.x;
        Ws[lk + 1][lm] = wv.y;
        Ws[lk + 2][lm] = wv.z;
        Ws[lk + 3][lm] = wv.w;

        __syncthreads();

        #pragma unroll
        for (int kk = 0; kk < 16; kk++) {
            float4 a4 = *(const float4*)&As[kk][ty * 4];
            float4 w4 = *(const float4*)&Ws[kk][tx * 4];
            acc[0][0] += a4.x * w4.x; acc[0][1] += a4.x * w4.y;
            acc[0][2] += a4.x * w4.z; acc[0][3] += a4.x * w4.w;
            acc[1][0] += a4.y * w4.x; acc[1][1] += a4.y * w4.y;
            acc[1][2] += a4.y * w4.z; acc[1][3] += a4.y * w4.w;
            acc[2][0] += a4.z * w4.x; acc[2][1] += a4.z * w4.y;
            acc[2][2] += a4.z * w4.z; acc[2][3] += a4.z * w4.w;
            acc[3][0] += a4.w * w4.x; acc[3][1] += a4.w * w4.y;
            acc[3][2] += a4.w * w4.z; acc[3][3] += a4.w * w4.w;
        }
        __syncthreads();
    }

    #pragma unroll
    for (int i = 0; i < 4; i++) {
        int m = bm + ty * 4 + i;
        #pragma unroll
        for (int j = 0; j < 4; j++) {
            int n = bn + tx * 4 + j;
            if (n < N)
                C[(size_t)m * N + n] = acc[i][j] + b1[n] + b2[n];
        }
    }
}

// ---------------------------------------------------------------------------
// Recurrent scan for one layer. One CTA per batch row.
// W_hh (200x200) resident in smem, row-padded to 204 floats so that
// per-thread LDS.128 with inter-lane stride 204 words is conflict-free
// (stride mod 32 = 12 -> 8 distinct banks per 8-lane phase).
// h double-buffered in static smem; one __syncthreads per step.
// ---------------------------------------------------------------------------
#define WPAD 204
#define RNN_SMEM (H * WPAD * 4)

__global__ __launch_bounds__(256)
void rnn_scan(const float* __restrict__ pre,
              const float* __restrict__ W_hh,
              float* __restrict__ hseq) {
    extern __shared__ float Wsm[];                      // [200][204]
    __shared__ __align__(16) float hbuf[2][208];

    const int b = blockIdx.x;
    const int tid = threadIdx.x;

    // load W_hh into padded smem (coalesced global reads)
    for (int i = tid; i < H * H; i += blockDim.x) {
        int j = i / H, k = i % H;
        Wsm[j * WPAD + k] = W_hh[i];
    }
    if (tid < 208) { hbuf[0][tid] = 0.f; hbuf[1][tid] = 0.f; }
    __syncthreads();

    const float* preb = pre + (size_t)b * T * H;
    float* outb = hseq + (size_t)b * T * H;

    int cur = 0;
    for (int t = 0; t < T; t++) {
        if (tid < H) {
            float acc = preb[t * H + tid];
            const float* wrow = &Wsm[tid * WPAD];
            #pragma unroll 10
            for (int k = 0; k < H; k += 4) {
                float4 w4 = *(const float4*)&wrow[k];
                float4 h4 = *(const float4*)&hbuf[cur][k];
                acc += w4.x * h4.x + w4.y * h4.y + w4.z * h4.z + w4.w * h4.w;
            }
            float val = tanhf(acc);
            hbuf[cur ^ 1][tid] = val;    // write next buffer (no race w/ cur reads)
            outb[t * H + tid] = val;
        }
        __syncthreads();
        cur ^= 1;
    }
}

// ---------------------------------------------------------------------------
// Final FC: logits[b,c] = h_last[b,:] . fc_w[c,:] + fc_b[c]
// ---------------------------------------------------------------------------
__global__ void fc_kernel(const float* __restrict__ hseq,
                          const float* __restrict__ fc_w,
                          const float* __restrict__ fc_b,
                          float* __restrict__ out) {
    int tid = threadIdx.x;               // 64 threads
    if (tid >= B * NCLS) return;
    int bb = tid >> 1;
    int c  = tid & 1;
    const float* h = hseq + ((size_t)bb * T + (T - 1)) * H;
    const float* w = fc_w + c * H;
    float acc = fc_b[c];
    #pragma unroll 8
    for (int k = 0; k < H; k++) acc += h[k] * w[k];
    out[bb * NCLS + c] = acc;
}

// ---------------------------------------------------------------------------
// Launch
// ---------------------------------------------------------------------------
extern "C" void kernel_launch(void* const* d_in, const int* in_sizes, int n_in,
                              void* d_out, int out_size) {
    const float* x     = (const float*)d_in[0];
    const float* W_ih0 = (const float*)d_in[1];
    const float* W_hh0 = (const float*)d_in[2];
    const float* b_ih0 = (const float*)d_in[3];
    const float* b_hh0 = (const float*)d_in[4];
    const float* W_ih1 = (const float*)d_in[5];
    const float* W_hh1 = (const float*)d_in[6];
    const float* b_ih1 = (const float*)d_in[7];
    const float* b_hh1 = (const float*)d_in[8];
    const float* W_ih2 = (const float*)d_in[9];
    const float* W_hh2 = (const float*)d_in[10];
    const float* b_ih2 = (const float*)d_in[11];
    const float* b_hh2 = (const float*)d_in[12];
    const float* fc_w  = (const float*)d_in[13];
    const float* fc_b  = (const float*)d_in[14];

    float *pre, *h;
    cudaGetSymbolAddress((void**)&pre, g_pre);
    cudaGetSymbolAddress((void**)&h,   g_h);

    cudaFuncSetAttribute(rnn_scan, cudaFuncAttributeMaxDynamicSharedMemorySize, RNN_SMEM);

    dim3 gg((H + 63) / 64, M_TOT / 64);   // (4, 32)

    gemm_abt_bias<<<gg, 256>>>(x, W_ih0, b_ih0, b_hh0, pre, M_TOT, H, DIN);
    rnn_scan<<<B, 256, RNN_SMEM>>>(pre, W_hh0, h);

    gemm_abt_bias<<<gg, 256>>>(h, W_ih1, b_ih1, b_hh1, pre, M_TOT, H, H);
    rnn_scan<<<B, 256, RNN_SMEM>>>(pre, W_hh1, h);

    gemm_abt_bias<<<gg, 256>>>(h, W_ih2, b_ih2, b_hh2, pre, M_TOT, H, H);
    rnn_scan<<<B, 256, RNN_SMEM>>>(pre, W_hh2, h);

    fc_kernel<<<1, 64>>>(h, fc_w, fc_b, (float*)d_out);
}

// round 3
// speedup vs baseline: 1.9370x; 1.9370x over previous
#include <cuda_runtime.h>
#include <cuda_bf16.h>

// Problem dims (fixed)
#define B    32
#define T    64
#define DIN  10000
#define H    200
#define NCLS 2
#define M_TOT (B * T)          // 2048

#define KSPLIT 4
#define KCHUNK 2500            // DIN / KSPLIT
#define GBM 128
#define GBN 128
#define GBK 16

// Scratch (device globals: no allocation allowed)
__device__ float g_pre[M_TOT * H];
__device__ float g_h[M_TOT * H];
__device__ float g_part[KSPLIT * M_TOT * H];   // 6.55 MB partial sums

// ---------------------------------------------------------------------------
// Layer-0 GEMM: part[z][m][n] = sum_{k in chunk z} x[m,k] * W[n,k]
// 128x128 tile, BK=16, 8x8 microtile -> 4 FMA per smem word (FMA-balanced).
// grid (2, 16, 4) = 128 CTAs, one per SM, no tail.
// ---------------------------------------------------------------------------
__global__ __launch_bounds__(256, 1)
void gemm0(const float* __restrict__ A,
           const float* __restrict__ W,
           float* __restrict__ part) {
    __shared__ float As[GBK][GBM];
    __shared__ float Bs[GBK][GBN];

    const int bn = blockIdx.x * GBN;
    const int bm = blockIdx.y * GBM;
    const int kz = blockIdx.z;
    const int kbeg = kz * KCHUNK;
    const int kend = kbeg + KCHUNK;

    const int tid = threadIdx.x;
    const int tx = tid % 16;        // n micro
    const int ty = tid / 16;        // m micro

    float acc[8][8] = {};

    for (int k0 = kbeg; k0 < kend; k0 += GBK) {
        // each thread loads 2 float4 of A and 2 of W (transposed store to smem)
        #pragma unroll
        for (int u = 0; u < 2; u++) {
            int idx = tid + u * 256;        // 0..511 float4 slots
            int row = idx >> 2;             // 0..127
            int kq  = (idx & 3) * 4;        // 0,4,8,12
            int kg  = k0 + kq;
            bool kok = (kg + 4 <= kend);    // chunk & K are multiples of 4

            float4 av = make_float4(0.f, 0.f, 0.f, 0.f);
            if (kok) av = *(const float4*)&A[(size_t)(bm + row) * DIN + kg];
            As[kq + 0][row] = av.x;
            As[kq + 1][row] = av.y;
            As[kq + 2][row] = av.z;
            As[kq + 3][row] = av.w;

            int n = bn + row;
            float4 wv = make_float4(0.f, 0.f, 0.f, 0.f);
            if (kok && n < H) wv = *(const float4*)&W[(size_t)n * DIN + kg];
            Bs[kq + 0][row] = wv.x;
            Bs[kq + 1][row] = wv.y;
            Bs[kq + 2][row] = wv.z;
            Bs[kq + 3][row] = wv.w;
        }
        __syncthreads();

        #pragma unroll
        for (int kk = 0; kk < GBK; kk++) {
            float a[8], bv[8];
            *(float4*)&a[0]  = *(const float4*)&As[kk][ty * 8];
            *(float4*)&a[4]  = *(const float4*)&As[kk][ty * 8 + 4];
            *(float4*)&bv[0] = *(const float4*)&Bs[kk][tx * 8];
            *(float4*)&bv[4] = *(const float4*)&Bs[kk][tx * 8 + 4];
            #pragma unroll
            for (int i = 0; i < 8; i++)
                #pragma unroll
                for (int j = 0; j < 8; j++)
                    acc[i][j] += a[i] * bv[j];
        }
        __syncthreads();
    }

    float* pz = part + (size_t)kz * M_TOT * H;
    #pragma unroll
    for (int i = 0; i < 8; i++) {
        int m = bm + ty * 8 + i;
        #pragma unroll
        for (int j = 0; j < 8; j++) {
            int n = bn + tx * 8 + j;
            if (n < H) pz[(size_t)m * H + n] = acc[i][j];
        }
    }
}

// Sum K-split partials + both biases -> pre
__global__ void reduce_bias(const float* __restrict__ part,
                            const float* __restrict__ b1,
                            const float* __restrict__ b2,
                            float* __restrict__ pre) {
    int i = blockIdx.x * blockDim.x + threadIdx.x;
    if (i >= M_TOT * H) return;
    const int MH = M_TOT * H;
    int n = i % H;
    pre[i] = part[i] + part[i + MH] + part[i + 2 * MH] + part[i + 3 * MH]
           + b1[n] + b2[n];
}

// ---------------------------------------------------------------------------
// GEMM for K=200 layers: C[m,n] = sum_k A[m,k]*W[n,k] + b1[n] + b2[n]
// (64x64 tile, 4x4 microtile — small K, good enough)
// ---------------------------------------------------------------------------
__global__ __launch_bounds__(256)
void gemm_abt_bias(const float* __restrict__ A,
                   const float* __restrict__ W,
                   const float* __restrict__ b1,
                   const float* __restrict__ b2,
                   float* __restrict__ C,
                   int M, int N, int K) {
    __shared__ float As[16][64];
    __shared__ float Ws[16][64];

    const int bm = blockIdx.y * 64;
    const int bn = blockIdx.x * 64;
    const int tid = threadIdx.x;
    const int tx = tid % 16;
    const int ty = tid / 16;
    const int lm = tid / 4;
    const int lk = (tid % 4) * 4;

    float acc[4][4] = {};

    for (int k0 = 0; k0 < K; k0 += 16) {
        const int kbase = k0 + lk;
        const bool kok = (kbase < K);

        float4 av = make_float4(0.f, 0.f, 0.f, 0.f);
        if (kok) av = *(const float4*)&A[(size_t)(bm + lm) * K + kbase];
        As[lk + 0][lm] = av.x; As[lk + 1][lm] = av.y;
        As[lk + 2][lm] = av.z; As[lk + 3][lm] = av.w;

        float4 wv = make_float4(0.f, 0.f, 0.f, 0.f);
        int n = bn + lm;
        if (kok && n < N) wv = *(const float4*)&W[(size_t)n * K + kbase];
        Ws[lk + 0][lm] = wv.x; Ws[lk + 1][lm] = wv.y;
        Ws[lk + 2][lm] = wv.z; Ws[lk + 3][lm] = wv.w;

        __syncthreads();

        #pragma unroll
        for (int kk = 0; kk < 16; kk++) {
            float4 a4 = *(const float4*)&As[kk][ty * 4];
            float4 w4 = *(const float4*)&Ws[kk][tx * 4];
            acc[0][0] += a4.x * w4.x; acc[0][1] += a4.x * w4.y;
            acc[0][2] += a4.x * w4.z; acc[0][3] += a4.x * w4.w;
            acc[1][0] += a4.y * w4.x; acc[1][1] += a4.y * w4.y;
            acc[1][2] += a4.y * w4.z; acc[1][3] += a4.y * w4.w;
            acc[2][0] += a4.z * w4.x; acc[2][1] += a4.z * w4.y;
            acc[2][2] += a4.z * w4.z; acc[2][3] += a4.z * w4.w;
            acc[3][0] += a4.w * w4.x; acc[3][1] += a4.w * w4.y;
            acc[3][2] += a4.w * w4.z; acc[3][3] += a4.w * w4.w;
        }
        __syncthreads();
    }

    #pragma unroll
    for (int i = 0; i < 4; i++) {
        int m = bm + ty * 4 + i;
        #pragma unroll
        for (int j = 0; j < 4; j++) {
            int n = bn + tx * 4 + j;
            if (n < N)
                C[(size_t)m * N + n] = acc[i][j] + b1[n] + b2[n];
        }
    }
}

// ---------------------------------------------------------------------------
// Recurrent scan: one CTA per batch row, 800 threads = 4 k-splits x 200 outputs.
// W_hh held in REGISTERS: thread (n, q) holds W[n, k] for k = q*4 + 16j,
// j = 0..12 (13 float4 = 52 regs). h vector read broadcast from smem.
// pre[] for all T steps staged in dynamic smem. 2 barriers per step.
// ---------------------------------------------------------------------------
#define SCAN_THREADS 800
#define SCAN_SMEM (T * H * 4)    // 51200 B for pre staging

__global__ __launch_bounds__(SCAN_THREADS, 1)
void rnn_scan(const float* __restrict__ pre,
              const float* __restrict__ W_hh,
              float* __restrict__ hseq) {
    extern __shared__ float pres[];                    // [T*H]
    __shared__ __align__(16) float hbuf[2][208];
    __shared__ float partial[4][208];

    const int b = blockIdx.x;
    const int tid = threadIdx.x;
    const int n = tid % H;        // output index
    const int q = tid / H;        // k-split 0..3

    // W rows into registers (zero-fill the two out-of-range tail float4s)
    float4 wr[13];
    #pragma unroll
    for (int j = 0; j < 13; j++) {
        int k = q * 4 + 16 * j;
        if (k + 4 <= H)
            wr[j] = *(const float4*)&W_hh[(size_t)n * H + k];
        else
            wr[j] = make_float4(0.f, 0.f, 0.f, 0.f);
    }

    // stage all pre for this batch row
    const float* preb = pre + (size_t)b * T * H;
    for (int i = tid; i < T * H; i += SCAN_THREADS) pres[i] = preb[i];
    if (tid < 208) { hbuf[0][tid] = 0.f; hbuf[1][tid] = 0.f; }
    __syncthreads();

    float* outb = hseq + (size_t)b * T * H;

    int cur = 0;
    for (int t = 0; t < T; t++) {
        float s0 = 0.f, s1 = 0.f, s2 = 0.f, s3 = 0.f;
        #pragma unroll
        for (int j = 0; j < 13; j++) {
            int k = q * 4 + 16 * j;                    // <= 204; hbuf padded to 208
            float4 h4 = *(const float4*)&hbuf[cur][k];
            s0 += wr[j].x * h4.x;
            s1 += wr[j].y * h4.y;
            s2 += wr[j].z * h4.z;
            s3 += wr[j].w * h4.w;
        }
        partial[q][n] = (s0 + s1) + (s2 + s3);
        __syncthreads();

        if (tid < H) {
            float v = tanhf(pres[t * H + tid]
                            + partial[0][tid] + partial[1][tid]
                            + partial[2][tid] + partial[3][tid]);
            hbuf[cur ^ 1][tid] = v;
            outb[t * H + tid] = v;
        }
        __syncthreads();
        cur ^= 1;
    }
}

// ---------------------------------------------------------------------------
// Final FC
// ---------------------------------------------------------------------------
__global__ void fc_kernel(const float* __restrict__ hseq,
                          const float* __restrict__ fc_w,
                          const float* __restrict__ fc_b,
                          float* __restrict__ out) {
    int tid = threadIdx.x;
    if (tid >= B * NCLS) return;
    int bb = tid >> 1;
    int c  = tid & 1;
    const float* h = hseq + ((size_t)bb * T + (T - 1)) * H;
    const float* w = fc_w + c * H;
    float acc = fc_b[c];
    #pragma unroll 8
    for (int k = 0; k < H; k++) acc += h[k] * w[k];
    out[bb * NCLS + c] = acc;
}

// ---------------------------------------------------------------------------
// Launch
// ---------------------------------------------------------------------------
extern "C" void kernel_launch(void* const* d_in, const int* in_sizes, int n_in,
                              void* d_out, int out_size) {
    const float* x     = (const float*)d_in[0];
    const float* W_ih0 = (const float*)d_in[1];
    const float* W_hh0 = (const float*)d_in[2];
    const float* b_ih0 = (const float*)d_in[3];
    const float* b_hh0 = (const float*)d_in[4];
    const float* W_ih1 = (const float*)d_in[5];
    const float* W_hh1 = (const float*)d_in[6];
    const float* b_ih1 = (const float*)d_in[7];
    const float* b_hh1 = (const float*)d_in[8];
    const float* W_ih2 = (const float*)d_in[9];
    const float* W_hh2 = (const float*)d_in[10];
    const float* b_ih2 = (const float*)d_in[11];
    const float* b_hh2 = (const float*)d_in[12];
    const float* fc_w  = (const float*)d_in[13];
    const float* fc_b  = (const float*)d_in[14];

    float *pre, *h, *part;
    cudaGetSymbolAddress((void**)&pre,  g_pre);
    cudaGetSymbolAddress((void**)&h,    g_h);
    cudaGetSymbolAddress((void**)&part, g_part);

    cudaFuncSetAttribute(rnn_scan, cudaFuncAttributeMaxDynamicSharedMemorySize, SCAN_SMEM);

    // Layer 0: big GEMM (K-split) + reduce + scan
    gemm0<<<dim3(2, 16, KSPLIT), 256>>>(x, W_ih0, part);
    reduce_bias<<<(M_TOT * H + 255) / 256, 256>>>(part, b_ih0, b_hh0, pre);
    rnn_scan<<<B, SCAN_THREADS, SCAN_SMEM>>>(pre, W_hh0, h);

    dim3 gg((H + 63) / 64, M_TOT / 64);   // (4, 32)

    // Layer 1
    gemm_abt_bias<<<gg, 256>>>(h, W_ih1, b_ih1, b_hh1, pre, M_TOT, H, H);
    rnn_scan<<<B, SCAN_THREADS, SCAN_SMEM>>>(pre, W_hh1, h);

    // Layer 2
    gemm_abt_bias<<<gg, 256>>>(h, W_ih2, b_ih2, b_hh2, pre, M_TOT, H, H);
    rnn_scan<<<B, SCAN_THREADS, SCAN_SMEM>>>(pre, W_hh2, h);

    fc_kernel<<<1, 64>>>(h, fc_w, fc_b, (float*)d_out);
}

// round 5
// speedup vs baseline: 3.7538x; 1.9379x over previous
#include <cuda_runtime.h>
#include <cuda_bf16.h>
#include <cstdint>

// Problem dims (fixed)
#define B    32
#define T    64
#define DIN  10000
#define H    200
#define NCLS 2
#define M_TOT (B * T)          // 2048
#define KPAD 10240             // DIN padded to multiple of 64

#define KSPLIT 8
#define KC    (KPAD / KSPLIT)  // 1280
#define KB    64               // k per smem chunk
#define NCHUNK (KC / KB)       // 20

#define NPAD 224               // CTA N tile (200 real + 24 zero pad)
#define SMSTRIDE 72            // bf16 elems per smem row (64 + 8 pad)
#define ROWB (SMSTRIDE * 2)    // 144 bytes

// smem buffer layout (bytes, per stage)
#define OFF_AH 0
#define OFF_AL (128 * ROWB)                 // 18432
#define OFF_WH (2 * 128 * ROWB)             // 36864
#define OFF_WL (2 * 128 * ROWB + NPAD * ROWB)   // 69120
#define BUFB   (2 * 128 * ROWB + 2 * NPAD * ROWB)  // 101376
#define GEMM_SMEM (2 * BUFB)                // 202752

// Scratch (device globals: no allocation allowed)
__device__ float g_pre[M_TOT * H];
__device__ float g_h[M_TOT * H];
__device__ float g_part[KSPLIT * M_TOT * H];
__device__ __nv_bfloat16 g_Ahi[(size_t)M_TOT * KPAD];
__device__ __nv_bfloat16 g_Alo[(size_t)M_TOT * KPAD];
__device__ __nv_bfloat16 g_Whi[(size_t)H * KPAD];
__device__ __nv_bfloat16 g_Wlo[(size_t)H * KPAD];

// ---------------------------------------------------------------------------
// Helpers: cp.async + mma.sync (baseline PTX, compiles for sm_103)
// ---------------------------------------------------------------------------
__device__ __forceinline__ void cp16(void* dst, const void* src, int srcsize) {
    uint32_t d = (uint32_t)__cvta_generic_to_shared(dst);
    asm volatile("cp.async.cg.shared.global [%0], [%1], 16, %2;"
                 :: "r"(d), "l"(src), "r"(srcsize) : "memory");
}
__device__ __forceinline__ void cp_commit() {
    asm volatile("cp.async.commit_group;" ::: "memory");
}
template <int N>
__device__ __forceinline__ void cp_wait() {
    asm volatile("cp.async.wait_group %0;" :: "n"(N) : "memory");
}
__device__ __forceinline__ void mma_bf16(float* c, const uint32_t* a,
                                         uint32_t b0, uint32_t b1) {
    asm volatile(
        "mma.sync.aligned.m16n8k16.row.col.f32.bf16.bf16.f32 "
        "{%0,%1,%2,%3}, {%4,%5,%6,%7}, {%8,%9}, {%0,%1,%2,%3};"
        : "+f"(c[0]), "+f"(c[1]), "+f"(c[2]), "+f"(c[3])
        : "r"(a[0]), "r"(a[1]), "r"(a[2]), "r"(a[3]), "r"(b0), "r"(b1));
}
__device__ __forceinline__ uint32_t lds32(const char* base, int row, int col_bf16) {
    return *(const uint32_t*)(base + row * ROWB + col_bf16 * 2);
}

// ---------------------------------------------------------------------------
// Split-convert fp32 -> (hi, lo) bf16, zero-padded K -> KPAD. 4 elems/thread.
// ---------------------------------------------------------------------------
__global__ void cvt_split4(const float* __restrict__ src,
                           __nv_bfloat16* __restrict__ hi,
                           __nv_bfloat16* __restrict__ lo,
                           int rows, int K) {
    int i = blockIdx.x * blockDim.x + threadIdx.x;
    int per_row = KPAD / 4;
    if (i >= rows * per_row) return;
    int r = i / per_row;
    int k4 = (i % per_row) * 4;

    float4 v = make_float4(0.f, 0.f, 0.f, 0.f);
    if (k4 < K) v = *(const float4*)&src[(size_t)r * K + k4];   // K % 4 == 0

    __nv_bfloat16 h[4], l[4];
    float vv[4] = {v.x, v.y, v.z, v.w};
    #pragma unroll
    for (int j = 0; j < 4; j++) {
        h[j] = __float2bfloat16(vv[j]);
        l[j] = __float2bfloat16(vv[j] - __bfloat162float(h[j]));
    }
    size_t o = (size_t)r * KPAD + k4;
    *(uint2*)&hi[o] = *(uint2*)h;
    *(uint2*)&lo[o] = *(uint2*)l;
}

// ---------------------------------------------------------------------------
// Layer-0 GEMM on HMMA: part[z][m][n] = sum_{k in chunk z} A[m,k]*W[n,k]
// bf16 3-term split, fp32 accum. 128 CTAs (8 ksplit x 16 mtiles), 512 thr.
// Warp grid 4(m) x 4(n): warp tile m32 x n56 (7 n8-blocks), 2 m16 sub-tiles.
// cp.async double-buffered k=64 chunks. Smem rows padded to 72 bf16 so every
// fragment LDS.32 hits bank==lane (conflict-free).
// ---------------------------------------------------------------------------
__device__ __forceinline__ void load_chunk(char* base,
                                           const __nv_bfloat16* Amh,
                                           const __nv_bfloat16* Aml,
                                           const __nv_bfloat16* Wh,
                                           const __nv_bfloat16* Wl,
                                           int k0, int tid) {
    // A: 128 rows x 8 16B-quads, hi+lo
    #pragma unroll
    for (int i = tid; i < 1024; i += 512) {
        int r = i >> 3, q = i & 7;
        int off = r * ROWB + q * 16;
        size_t go = (size_t)r * KPAD + k0 + q * 8;
        cp16(base + OFF_AH + off, Amh + go, 16);
        cp16(base + OFF_AL + off, Aml + go, 16);
    }
    // W: 224 rows x 8 quads, rows >= 200 zero-filled (src-size 0)
    #pragma unroll
    for (int i = tid; i < NPAD * 8; i += 512) {
        int r = i >> 3, q = i & 7;
        int off = r * ROWB + q * 16;
        int rr = r < H ? r : H - 1;
        int sz = r < H ? 16 : 0;
        size_t go = (size_t)rr * KPAD + k0 + q * 8;
        cp16(base + OFF_WH + off, Wh + go, sz);
        cp16(base + OFF_WL + off, Wl + go, sz);
    }
}

__global__ __launch_bounds__(512, 1)
void gemm0_mma(const __nv_bfloat16* __restrict__ Ahi,
               const __nv_bfloat16* __restrict__ Alo,
               const __nv_bfloat16* __restrict__ Whi,
               const __nv_bfloat16* __restrict__ Wlo,
               float* __restrict__ part) {
    extern __shared__ char sm[];

    const int tid  = threadIdx.x;
    const int wid  = tid >> 5;
    const int lane = tid & 31;
    const int grp  = lane >> 2;        // 0..7
    const int tig  = lane & 3;         // 0..3
    const int wm   = wid & 3;          // m warp 0..3
    const int wn   = wid >> 2;         // n warp 0..3

    const int kz   = blockIdx.x;
    const int bm   = blockIdx.y * 128;
    const int kbeg = kz * KC;

    const __nv_bfloat16* Amh = Ahi + (size_t)bm * KPAD;
    const __nv_bfloat16* Aml = Alo + (size_t)bm * KPAD;

    float acc[2][7][4] = {};

    // preload chunk 0
    load_chunk(sm, Amh, Aml, Whi, Wlo, kbeg, tid);
    cp_commit();

    for (int c = 0; c < NCHUNK; c++) {
        char* buf = sm + (c & 1) * BUFB;

        if (c + 1 < NCHUNK) {
            load_chunk(sm + ((c + 1) & 1) * BUFB, Amh, Aml, Whi, Wlo,
                       kbeg + (c + 1) * KB, tid);
            cp_commit();
            cp_wait<1>();
        } else {
            cp_wait<0>();
        }
        __syncthreads();

        const char* Ah = buf + OFF_AH;
        const char* Al = buf + OFF_AL;
        const char* Wh = buf + OFF_WH;
        const char* Wl = buf + OFF_WL;

        #pragma unroll
        for (int ks = 0; ks < 4; ks++) {
            const int kc = ks * 16 + tig * 2;
            uint32_t ah[2][4], al[2][4];
            #pragma unroll
            for (int mt = 0; mt < 2; mt++) {
                int r = wm * 32 + mt * 16 + grp;
                ah[mt][0] = lds32(Ah, r,     kc);
                ah[mt][1] = lds32(Ah, r + 8, kc);
                ah[mt][2] = lds32(Ah, r,     kc + 8);
                ah[mt][3] = lds32(Ah, r + 8, kc + 8);
                al[mt][0] = lds32(Al, r,     kc);
                al[mt][1] = lds32(Al, r + 8, kc);
                al[mt][2] = lds32(Al, r,     kc + 8);
                al[mt][3] = lds32(Al, r + 8, kc + 8);
            }
            #pragma unroll
            for (int j = 0; j < 7; j++) {
                int n = wn * 56 + j * 8 + grp;
                uint32_t bh0 = lds32(Wh, n, kc);
                uint32_t bh1 = lds32(Wh, n, kc + 8);
                uint32_t bl0 = lds32(Wl, n, kc);
                uint32_t bl1 = lds32(Wl, n, kc + 8);
                mma_bf16(acc[0][j], ah[0], bh0, bh1);   // Ahi*Whi
                mma_bf16(acc[1][j], ah[1], bh0, bh1);
                mma_bf16(acc[0][j], al[0], bh0, bh1);   // Alo*Whi
                mma_bf16(acc[1][j], al[1], bh0, bh1);
                mma_bf16(acc[0][j], ah[0], bl0, bl1);   // Ahi*Wlo
                mma_bf16(acc[1][j], ah[1], bl0, bl1);
            }
        }
        __syncthreads();
    }

    // epilogue: write fp32 partials
    float* pz = part + (size_t)kz * M_TOT * H;
    #pragma unroll
    for (int mt = 0; mt < 2; mt++) {
        #pragma unroll
        for (int j = 0; j < 7; j++) {
            int n = wn * 56 + j * 8 + tig * 2;
            if (n >= H) continue;
            int m0 = bm + wm * 32 + mt * 16 + grp;
            *(float2*)&pz[(size_t)m0 * H + n]       = make_float2(acc[mt][j][0], acc[mt][j][1]);
            *(float2*)&pz[(size_t)(m0 + 8) * H + n] = make_float2(acc[mt][j][2], acc[mt][j][3]);
        }
    }
}

// Sum K-split partials + both biases -> pre
__global__ void reduce_bias(const float* __restrict__ part,
                            const float* __restrict__ b1,
                            const float* __restrict__ b2,
                            float* __restrict__ pre) {
    int i = blockIdx.x * blockDim.x + threadIdx.x;
    if (i >= M_TOT * H) return;
    const int MH = M_TOT * H;
    int n = i % H;
    float s = b1[n] + b2[n];
    #pragma unroll
    for (int z = 0; z < KSPLIT; z++) s += part[i + (size_t)z * MH];
    pre[i] = s;
}

// ---------------------------------------------------------------------------
// GEMM for K=200 layers (SIMT, small)
// ---------------------------------------------------------------------------
__global__ __launch_bounds__(256)
void gemm_abt_bias(const float* __restrict__ A,
                   const float* __restrict__ W,
                   const float* __restrict__ b1,
                   const float* __restrict__ b2,
                   float* __restrict__ C,
                   int M, int N, int K) {
    __shared__ float As[16][64];
    __shared__ float Ws[16][64];

    const int bm = blockIdx.y * 64;
    const int bn = blockIdx.x * 64;
    const int tid = threadIdx.x;
    const int tx = tid % 16;
    const int ty = tid / 16;
    const int lm = tid / 4;
    const int lk = (tid % 4) * 4;

    float acc[4][4] = {};

    for (int k0 = 0; k0 < K; k0 += 16) {
        const int kbase = k0 + lk;
        const bool kok = (kbase < K);

        float4 av = make_float4(0.f, 0.f, 0.f, 0.f);
        if (kok) av = *(const float4*)&A[(size_t)(bm + lm) * K + kbase];
        As[lk + 0][lm] = av.x; As[lk + 1][lm] = av.y;
        As[lk + 2][lm] = av.z; As[lk + 3][lm] = av.w;

        float4 wv = make_float4(0.f, 0.f, 0.f, 0.f);
        int n = bn + lm;
        if (kok && n < N) wv = *(const float4*)&W[(size_t)n * K + kbase];
        Ws[lk + 0][lm] = wv.x; Ws[lk + 1][lm] = wv.y;
        Ws[lk + 2][lm] = wv.z; Ws[lk + 3][lm] = wv.w;

        __syncthreads();

        #pragma unroll
        for (int kk = 0; kk < 16; kk++) {
            float4 a4 = *(const float4*)&As[kk][ty * 4];
            float4 w4 = *(const float4*)&Ws[kk][tx * 4];
            acc[0][0] += a4.x * w4.x; acc[0][1] += a4.x * w4.y;
            acc[0][2] += a4.x * w4.z; acc[0][3] += a4.x * w4.w;
            acc[1][0] += a4.y * w4.x; acc[1][1] += a4.y * w4.y;
            acc[1][2] += a4.y * w4.z; acc[1][3] += a4.y * w4.w;
            acc[2][0] += a4.z * w4.x; acc[2][1] += a4.z * w4.y;
            acc[2][2] += a4.z * w4.z; acc[2][3] += a4.z * w4.w;
            acc[3][0] += a4.w * w4.x; acc[3][1] += a4.w * w4.y;
            acc[3][2] += a4.w * w4.z; acc[3][3] += a4.w * w4.w;
        }
        __syncthreads();
    }

    #pragma unroll
    for (int i = 0; i < 4; i++) {
        int m = bm + ty * 4 + i;
        #pragma unroll
        for (int j = 0; j < 4; j++) {
            int n = bn + tx * 4 + j;
            if (n < N)
                C[(size_t)m * N + n] = acc[i][j] + b1[n] + b2[n];
        }
    }
}

// ---------------------------------------------------------------------------
// Recurrent scan: one CTA per batch row, 800 threads = 4 k-splits x 200 outputs.
// W_hh in registers; h broadcast from smem; pre staged in smem.
// ---------------------------------------------------------------------------
#define SCAN_THREADS 800
#define SCAN_SMEM (T * H * 4)

__global__ __launch_bounds__(SCAN_THREADS, 1)
void rnn_scan(const float* __restrict__ pre,
              const float* __restrict__ W_hh,
              float* __restrict__ hseq) {
    extern __shared__ float pres[];
    __shared__ __align__(16) float hbuf[2][208];
    __shared__ float partial[4][208];

    const int b = blockIdx.x;
    const int tid = threadIdx.x;
    const int n = tid % H;
    const int q = tid / H;

    float4 wr[13];
    #pragma unroll
    for (int j = 0; j < 13; j++) {
        int k = q * 4 + 16 * j;
        if (k + 4 <= H)
            wr[j] = *(const float4*)&W_hh[(size_t)n * H + k];
        else
            wr[j] = make_float4(0.f, 0.f, 0.f, 0.f);
    }

    const float* preb = pre + (size_t)b * T * H;
    for (int i = tid; i < T * H; i += SCAN_THREADS) pres[i] = preb[i];
    if (tid < 208) { hbuf[0][tid] = 0.f; hbuf[1][tid] = 0.f; }
    __syncthreads();

    float* outb = hseq + (size_t)b * T * H;

    int cur = 0;
    for (int t = 0; t < T; t++) {
        float s0 = 0.f, s1 = 0.f, s2 = 0.f, s3 = 0.f;
        #pragma unroll
        for (int j = 0; j < 13; j++) {
            int k = q * 4 + 16 * j;
            float4 h4 = *(const float4*)&hbuf[cur][k];
            s0 += wr[j].x * h4.x;
            s1 += wr[j].y * h4.y;
            s2 += wr[j].z * h4.z;
            s3 += wr[j].w * h4.w;
        }
        partial[q][n] = (s0 + s1) + (s2 + s3);
        __syncthreads();

        if (tid < H) {
            float v = tanhf(pres[t * H + tid]
                            + partial[0][tid] + partial[1][tid]
                            + partial[2][tid] + partial[3][tid]);
            hbuf[cur ^ 1][tid] = v;
            outb[t * H + tid] = v;
        }
        __syncthreads();
        cur ^= 1;
    }
}

// ---------------------------------------------------------------------------
// Final FC
// ---------------------------------------------------------------------------
__global__ void fc_kernel(const float* __restrict__ hseq,
                          const float* __restrict__ fc_w,
                          const float* __restrict__ fc_b,
                          float* __restrict__ out) {
    int tid = threadIdx.x;
    if (tid >= B * NCLS) return;
    int bb = tid >> 1;
    int c  = tid & 1;
    const float* h = hseq + ((size_t)bb * T + (T - 1)) * H;
    const float* w = fc_w + c * H;
    float acc = fc_b[c];
    #pragma unroll 8
    for (int k = 0; k < H; k++) acc += h[k] * w[k];
    out[bb * NCLS + c] = acc;
}

// ---------------------------------------------------------------------------
// Launch
// ---------------------------------------------------------------------------
extern "C" void kernel_launch(void* const* d_in, const int* in_sizes, int n_in,
                              void* d_out, int out_size) {
    const float* x     = (const float*)d_in[0];
    const float* W_ih0 = (const float*)d_in[1];
    const float* W_hh0 = (const float*)d_in[2];
    const float* b_ih0 = (const float*)d_in[3];
    const float* b_hh0 = (const float*)d_in[4];
    const float* W_ih1 = (const float*)d_in[5];
    const float* W_hh1 = (const float*)d_in[6];
    const float* b_ih1 = (const float*)d_in[7];
    const float* b_hh1 = (const float*)d_in[8];
    const float* W_ih2 = (const float*)d_in[9];
    const float* W_hh2 = (const float*)d_in[10];
    const float* b_ih2 = (const float*)d_in[11];
    const float* b_hh2 = (const float*)d_in[12];
    const float* fc_w  = (const float*)d_in[13];
    const float* fc_b  = (const float*)d_in[14];

    float *pre, *h, *part;
    __nv_bfloat16 *Ahi, *Alo, *Whi, *Wlo;
    cudaGetSymbolAddress((void**)&pre,  g_pre);
    cudaGetSymbolAddress((void**)&h,    g_h);
    cudaGetSymbolAddress((void**)&part, g_part);
    cudaGetSymbolAddress((void**)&Ahi,  g_Ahi);
    cudaGetSymbolAddress((void**)&Alo,  g_Alo);
    cudaGetSymbolAddress((void**)&Whi,  g_Whi);
    cudaGetSymbolAddress((void**)&Wlo,  g_Wlo);

    cudaFuncSetAttribute(rnn_scan, cudaFuncAttributeMaxDynamicSharedMemorySize, SCAN_SMEM);
    cudaFuncSetAttribute(gemm0_mma, cudaFuncAttributeMaxDynamicSharedMemorySize, GEMM_SMEM);

    // Layer 0: split-convert, HMMA GEMM (K-split), reduce, scan
    cvt_split4<<<(M_TOT * (KPAD / 4) + 255) / 256, 256>>>(x, Ahi, Alo, M_TOT, DIN);
    cvt_split4<<<(H * (KPAD / 4) + 255) / 256, 256>>>(W_ih0, Whi, Wlo, H, DIN);
    gemm0_mma<<<dim3(KSPLIT, M_TOT / 128), 512, GEMM_SMEM>>>(Ahi, Alo, Whi, Wlo, part);
    reduce_bias<<<(M_TOT * H + 255) / 256, 256>>>(part, b_ih0, b_hh0, pre);
    rnn_scan<<<B, SCAN_THREADS, SCAN_SMEM>>>(pre, W_hh0, h);

    dim3 gg((H + 63) / 64, M_TOT / 64);   // (4, 32)

    // Layer 1
    gemm_abt_bias<<<gg, 256>>>(h, W_ih1, b_ih1, b_hh1, pre, M_TOT, H, H);
    rnn_scan<<<B, SCAN_THREADS, SCAN_SMEM>>>(pre, W_hh1, h);

    // Layer 2
    gemm_abt_bias<<<gg, 256>>>(h, W_ih2, b_ih2, b_hh2, pre, M_TOT, H, H);
    rnn_scan<<<B, SCAN_THREADS, SCAN_SMEM>>>(pre, W_hh2, h);

    fc_kernel<<<1, 64>>>(h, fc_w, fc_b, (float*)d_out);
}

// round 6
// speedup vs baseline: 4.0339x; 1.0746x over previous
#include <cuda_runtime.h>
#include <cuda_bf16.h>
#include <cstdint>

// Problem dims (fixed)
#define B    32
#define T    64
#define DIN  10000
#define H    200
#define NCLS 2
#define M_TOT (B * T)          // 2048
#define KPAD 10240             // DIN padded to multiple of 64

#define KSPLIT 8
#define KC    (KPAD / KSPLIT)  // 1280
#define KB    64               // k per smem chunk
#define NCHUNK (KC / KB)       // 20

#define NPAD 224               // CTA N tile (200 real + 24 zero pad)
#define SMSTRIDE 72            // bf16 elems per smem row (64 + 8 pad)
#define ROWB (SMSTRIDE * 2)    // 144 bytes

// smem buffer layout (bytes, per stage)
#define OFF_AH 0
#define OFF_AL (128 * ROWB)                 // 18432
#define OFF_WH (2 * 128 * ROWB)             // 36864
#define OFF_WL (2 * 128 * ROWB + NPAD * ROWB)   // 69120
#define BUFB   (2 * 128 * ROWB + 2 * NPAD * ROWB)  // 101376
#define GEMM_SMEM (2 * BUFB)                // 202752

// Scratch (device globals: no allocation allowed)
__device__ float g_pre[M_TOT * H];
__device__ float g_h[M_TOT * H];
__device__ float g_part[KSPLIT * M_TOT * H];
__device__ __nv_bfloat16 g_Whi[(size_t)H * KPAD];
__device__ __nv_bfloat16 g_Wlo[(size_t)H * KPAD];

// ---------------------------------------------------------------------------
// Helpers
// ---------------------------------------------------------------------------
__device__ __forceinline__ void cp16(void* dst, const void* src, int srcsize) {
    uint32_t d = (uint32_t)__cvta_generic_to_shared(dst);
    asm volatile("cp.async.cg.shared.global [%0], [%1], 16, %2;"
                 :: "r"(d), "l"(src), "r"(srcsize) : "memory");
}
__device__ __forceinline__ void cp_commit() {
    asm volatile("cp.async.commit_group;" ::: "memory");
}
template <int N>
__device__ __forceinline__ void cp_wait() {
    asm volatile("cp.async.wait_group %0;" :: "n"(N) : "memory");
}
__device__ __forceinline__ void mma_bf16(float* c, const uint32_t* a,
                                         uint32_t b0, uint32_t b1) {
    asm volatile(
        "mma.sync.aligned.m16n8k16.row.col.f32.bf16.bf16.f32 "
        "{%0,%1,%2,%3}, {%4,%5,%6,%7}, {%8,%9}, {%0,%1,%2,%3};"
        : "+f"(c[0]), "+f"(c[1]), "+f"(c[2]), "+f"(c[3])
        : "r"(a[0]), "r"(a[1]), "r"(a[2]), "r"(a[3]), "r"(b0), "r"(b1));
}
__device__ __forceinline__ uint32_t lds32(const char* base, int row, int col_bf16) {
    return *(const uint32_t*)(base + row * ROWB + col_bf16 * 2);
}
// packed fp32x2 FMA: c.lo += a.lo*b.lo, c.hi += a.hi*b.hi (exact fp32 math)
__device__ __forceinline__ void fma2(unsigned long long& c,
                                     unsigned long long a, unsigned long long b) {
    asm("fma.rn.f32x2 %0, %1, %2, %3;" : "=l"(c) : "l"(a), "l"(b), "l"(c));
}
__device__ __forceinline__ float2 upk(unsigned long long v) {
    uint32_t lo, hi;
    asm("mov.b64 {%0,%1}, %2;" : "=r"(lo), "=r"(hi) : "l"(v));
    return make_float2(__uint_as_float(lo), __uint_as_float(hi));
}

// ---------------------------------------------------------------------------
// Split-convert fp32 -> (hi, lo) bf16, zero-padded K -> KPAD (W only now).
// ---------------------------------------------------------------------------
__global__ void cvt_split4(const float* __restrict__ src,
                           __nv_bfloat16* __restrict__ hi,
                           __nv_bfloat16* __restrict__ lo,
                           int rows, int K) {
    int i = blockIdx.x * blockDim.x + threadIdx.x;
    int per_row = KPAD / 4;
    if (i >= rows * per_row) return;
    int r = i / per_row;
    int k4 = (i % per_row) * 4;

    float4 v = make_float4(0.f, 0.f, 0.f, 0.f);
    if (k4 < K) v = *(const float4*)&src[(size_t)r * K + k4];   // K % 4 == 0

    __nv_bfloat16 h[4], l[4];
    float vv[4] = {v.x, v.y, v.z, v.w};
    #pragma unroll
    for (int j = 0; j < 4; j++) {
        h[j] = __float2bfloat16(vv[j]);
        l[j] = __float2bfloat16(vv[j] - __bfloat162float(h[j]));
    }
    size_t o = (size_t)r * KPAD + k4;
    *(uint2*)&hi[o] = *(uint2*)h;
    *(uint2*)&lo[o] = *(uint2*)l;
}

// ---------------------------------------------------------------------------
// Layer-0 GEMM on HMMA with fused fp32->bf16-split A conversion.
// part[z][m][n] = sum_{k in chunk z} x[m,k]*W[n,k]; bf16 3-term split.
// A path: LDG fp32 -> register split -> STS bf16 (overlapped with MMA).
// W path: cp.async from pre-converted Whi/Wlo.
// ---------------------------------------------------------------------------
__global__ __launch_bounds__(512, 1)
void gemm0_mma(const float* __restrict__ x,
               const __nv_bfloat16* __restrict__ Whi,
               const __nv_bfloat16* __restrict__ Wlo,
               float* __restrict__ part) {
    extern __shared__ char sm[];

    const int tid  = threadIdx.x;
    const int wid  = tid >> 5;
    const int lane = tid & 31;
    const int grp  = lane >> 2;        // 0..7
    const int tig  = lane & 3;         // 0..3
    const int wm   = wid & 3;          // m warp 0..3
    const int wn   = wid >> 2;         // n warp 0..3

    const int kz   = blockIdx.x;
    const int bm   = blockIdx.y * 128;
    const int kbeg = kz * KC;

    const float* Am = x + (size_t)bm * DIN;

    // A loader geometry: thread -> row ar, k-offsets asub+16u (u=0..3)
    const int ar   = tid >> 2;          // 0..127
    const int asub = (tid & 3) * 4;     // 0,4,8,12

    float4 areg[4];
    auto ldgA = [&](int k0) {
        #pragma unroll
        for (int u = 0; u < 4; u++) {
            int k = k0 + asub + 16 * u;
            if (k + 4 <= DIN)
                areg[u] = *(const float4*)&Am[(size_t)ar * DIN + k];
            else
                areg[u] = make_float4(0.f, 0.f, 0.f, 0.f);
        }
    };
    auto stsA = [&](char* buf) {
        #pragma unroll
        for (int u = 0; u < 4; u++) {
            int koff = asub + 16 * u;
            float v[4] = {areg[u].x, areg[u].y, areg[u].z, areg[u].w};
            __nv_bfloat16 h4[4], l4[4];
            #pragma unroll
            for (int j = 0; j < 4; j++) {
                h4[j] = __float2bfloat16(v[j]);
                l4[j] = __float2bfloat16(v[j] - __bfloat162float(h4[j]));
            }
            *(uint2*)(buf + OFF_AH + ar * ROWB + koff * 2) = *(uint2*)h4;
            *(uint2*)(buf + OFF_AL + ar * ROWB + koff * 2) = *(uint2*)l4;
        }
    };
    auto ldW = [&](char* buf, int k0) {
        #pragma unroll
        for (int i = tid; i < NPAD * 8; i += 512) {
            int r = i >> 3, q = i & 7;
            int off = r * ROWB + q * 16;
            int rr = r < H ? r : H - 1;
            int sz = r < H ? 16 : 0;
            size_t go = (size_t)rr * KPAD + k0 + q * 8;
            cp16(buf + OFF_WH + off, Whi + go, sz);
            cp16(buf + OFF_WL + off, Wlo + go, sz);
        }
    };

    float acc[2][7][4] = {};

    // prologue: chunk 0
    ldgA(kbeg);
    ldW(sm, kbeg);
    cp_commit();
    stsA(sm);
    cp_wait<0>();
    __syncthreads();

    for (int c = 0; c < NCHUNK; c++) {
        char* buf = sm + (c & 1) * BUFB;
        char* nbuf = sm + ((c + 1) & 1) * BUFB;

        if (c + 1 < NCHUNK) {
            ldgA(kbeg + (c + 1) * KB);
            ldW(nbuf, kbeg + (c + 1) * KB);
            cp_commit();
        }

        const char* Ah = buf + OFF_AH;
        const char* Al = buf + OFF_AL;
        const char* Wh = buf + OFF_WH;
        const char* Wl = buf + OFF_WL;

        #pragma unroll
        for (int ks = 0; ks < 4; ks++) {
            const int kc = ks * 16 + tig * 2;
            uint32_t ah[2][4], al[2][4];
            #pragma unroll
            for (int mt = 0; mt < 2; mt++) {
                int r = wm * 32 + mt * 16 + grp;
                ah[mt][0] = lds32(Ah, r,     kc);
                ah[mt][1] = lds32(Ah, r + 8, kc);
                ah[mt][2] = lds32(Ah, r,     kc + 8);
                ah[mt][3] = lds32(Ah, r + 8, kc + 8);
                al[mt][0] = lds32(Al, r,     kc);
                al[mt][1] = lds32(Al, r + 8, kc);
                al[mt][2] = lds32(Al, r,     kc + 8);
                al[mt][3] = lds32(Al, r + 8, kc + 8);
            }
            #pragma unroll
            for (int j = 0; j < 7; j++) {
                int n = wn * 56 + j * 8 + grp;
                uint32_t bh0 = lds32(Wh, n, kc);
                uint32_t bh1 = lds32(Wh, n, kc + 8);
                uint32_t bl0 = lds32(Wl, n, kc);
                uint32_t bl1 = lds32(Wl, n, kc + 8);
                mma_bf16(acc[0][j], ah[0], bh0, bh1);   // Ahi*Whi
                mma_bf16(acc[1][j], ah[1], bh0, bh1);
                mma_bf16(acc[0][j], al[0], bh0, bh1);   // Alo*Whi
                mma_bf16(acc[1][j], al[1], bh0, bh1);
                mma_bf16(acc[0][j], ah[0], bl0, bl1);   // Ahi*Wlo
                mma_bf16(acc[1][j], ah[1], bl0, bl1);
            }
        }

        if (c + 1 < NCHUNK) {
            stsA(nbuf);
            cp_wait<0>();
        }
        __syncthreads();
    }

    // epilogue: write fp32 partials
    float* pz = part + (size_t)kz * M_TOT * H;
    #pragma unroll
    for (int mt = 0; mt < 2; mt++) {
        #pragma unroll
        for (int j = 0; j < 7; j++) {
            int n = wn * 56 + j * 8 + tig * 2;
            if (n >= H) continue;
            int m0 = bm + wm * 32 + mt * 16 + grp;
            *(float2*)&pz[(size_t)m0 * H + n]       = make_float2(acc[mt][j][0], acc[mt][j][1]);
            *(float2*)&pz[(size_t)(m0 + 8) * H + n] = make_float2(acc[mt][j][2], acc[mt][j][3]);
        }
    }
}

// Sum K-split partials + both biases -> pre
__global__ void reduce_bias(const float* __restrict__ part,
                            const float* __restrict__ b1,
                            const float* __restrict__ b2,
                            float* __restrict__ pre) {
    int i = blockIdx.x * blockDim.x + threadIdx.x;
    if (i >= M_TOT * H) return;
    const int MH = M_TOT * H;
    int n = i % H;
    float s = b1[n] + b2[n];
    #pragma unroll
    for (int z = 0; z < KSPLIT; z++) s += part[i + (size_t)z * MH];
    pre[i] = s;
}

// ---------------------------------------------------------------------------
// GEMM for K=200 layers (SIMT, small)
// ---------------------------------------------------------------------------
__global__ __launch_bounds__(256)
void gemm_abt_bias(const float* __restrict__ A,
                   const float* __restrict__ W,
                   const float* __restrict__ b1,
                   const float* __restrict__ b2,
                   float* __restrict__ C,
                   int M, int N, int K) {
    __shared__ float As[16][64];
    __shared__ float Ws[16][64];

    const int bm = blockIdx.y * 64;
    const int bn = blockIdx.x * 64;
    const int tid = threadIdx.x;
    const int tx = tid % 16;
    const int ty = tid / 16;
    const int lm = tid / 4;
    const int lk = (tid % 4) * 4;

    float acc[4][4] = {};

    for (int k0 = 0; k0 < K; k0 += 16) {
        const int kbase = k0 + lk;
        const bool kok = (kbase < K);

        float4 av = make_float4(0.f, 0.f, 0.f, 0.f);
        if (kok) av = *(const float4*)&A[(size_t)(bm + lm) * K + kbase];
        As[lk + 0][lm] = av.x; As[lk + 1][lm] = av.y;
        As[lk + 2][lm] = av.z; As[lk + 3][lm] = av.w;

        float4 wv = make_float4(0.f, 0.f, 0.f, 0.f);
        int n = bn + lm;
        if (kok && n < N) wv = *(const float4*)&W[(size_t)n * K + kbase];
        Ws[lk + 0][lm] = wv.x; Ws[lk + 1][lm] = wv.y;
        Ws[lk + 2][lm] = wv.z; Ws[lk + 3][lm] = wv.w;

        __syncthreads();

        #pragma unroll
        for (int kk = 0; kk < 16; kk++) {
            float4 a4 = *(const float4*)&As[kk][ty * 4];
            float4 w4 = *(const float4*)&Ws[kk][tx * 4];
            acc[0][0] += a4.x * w4.x; acc[0][1] += a4.x * w4.y;
            acc[0][2] += a4.x * w4.z; acc[0][3] += a4.x * w4.w;
            acc[1][0] += a4.y * w4.x; acc[1][1] += a4.y * w4.y;
            acc[1][2] += a4.y * w4.z; acc[1][3] += a4.y * w4.w;
            acc[2][0] += a4.z * w4.x; acc[2][1] += a4.z * w4.y;
            acc[2][2] += a4.z * w4.z; acc[2][3] += a4.z * w4.w;
            acc[3][0] += a4.w * w4.x; acc[3][1] += a4.w * w4.y;
            acc[3][2] += a4.w * w4.z; acc[3][3] += a4.w * w4.w;
        }
        __syncthreads();
    }

    #pragma unroll
    for (int i = 0; i < 4; i++) {
        int m = bm + ty * 4 + i;
        #pragma unroll
        for (int j = 0; j < 4; j++) {
            int n = bn + tx * 4 + j;
            if (n < N)
                C[(size_t)m * N + n] = acc[i][j] + b1[n] + b2[n];
        }
    }
}

// ---------------------------------------------------------------------------
// Recurrent scan: one CTA per batch row, 800 threads = 4 k-splits x 200 outputs.
// W_hh in registers (packed f32x2 pairs); h broadcast from smem; dot products
// use fma.rn.f32x2 (2 fp32 MAC/instr) to double fp32 issue throughput.
// ---------------------------------------------------------------------------
#define SCAN_THREADS 800
#define SCAN_SMEM (T * H * 4)

__global__ __launch_bounds__(SCAN_THREADS, 1)
void rnn_scan(const float* __restrict__ pre,
              const float* __restrict__ W_hh,
              float* __restrict__ hseq) {
    extern __shared__ float pres[];
    __shared__ __align__(16) float hbuf[2][208];
    __shared__ float partial[4][208];

    const int b = blockIdx.x;
    const int tid = threadIdx.x;
    const int n = tid % H;
    const int q = tid / H;

    // W rows as packed f32x2 pairs (13 x 16B = 52 regs)
    ulonglong2 wr[13];
    #pragma unroll
    for (int j = 0; j < 13; j++) {
        int k = q * 4 + 16 * j;
        if (k + 4 <= H)
            wr[j] = *(const ulonglong2*)&W_hh[(size_t)n * H + k];
        else
            wr[j] = make_ulonglong2(0ull, 0ull);   // bits 0 == (0.f,0.f)
    }

    const float* preb = pre + (size_t)b * T * H;
    for (int i = tid; i < T * H; i += SCAN_THREADS) pres[i] = preb[i];
    if (tid < 208) { hbuf[0][tid] = 0.f; hbuf[1][tid] = 0.f; }
    __syncthreads();

    float* outb = hseq + (size_t)b * T * H;

    int cur = 0;
    for (int t = 0; t < T; t++) {
        unsigned long long a0 = 0ull, a1 = 0ull;
        #pragma unroll
        for (int j = 0; j < 13; j++) {
            int k = q * 4 + 16 * j;
            ulonglong2 h2 = *(const ulonglong2*)&hbuf[cur][k];
            fma2(a0, wr[j].x, h2.x);
            fma2(a1, wr[j].y, h2.y);
        }
        float2 p0 = upk(a0), p1 = upk(a1);
        partial[q][n] = (p0.x + p0.y) + (p1.x + p1.y);
        __syncthreads();

        if (tid < H) {
            float v = tanhf(pres[t * H + tid]
                            + partial[0][tid] + partial[1][tid]
                            + partial[2][tid] + partial[3][tid]);
            hbuf[cur ^ 1][tid] = v;
            outb[t * H + tid] = v;
        }
        __syncthreads();
        cur ^= 1;
    }
}

// ---------------------------------------------------------------------------
// Final FC
// ---------------------------------------------------------------------------
__global__ void fc_kernel(const float* __restrict__ hseq,
                          const float* __restrict__ fc_w,
                          const float* __restrict__ fc_b,
                          float* __restrict__ out) {
    int tid = threadIdx.x;
    if (tid >= B * NCLS) return;
    int bb = tid >> 1;
    int c  = tid & 1;
    const float* h = hseq + ((size_t)bb * T + (T - 1)) * H;
    const float* w = fc_w + c * H;
    float acc = fc_b[c];
    #pragma unroll 8
    for (int k = 0; k < H; k++) acc += h[k] * w[k];
    out[bb * NCLS + c] = acc;
}

// ---------------------------------------------------------------------------
// Launch
// ---------------------------------------------------------------------------
extern "C" void kernel_launch(void* const* d_in, const int* in_sizes, int n_in,
                              void* d_out, int out_size) {
    const float* x     = (const float*)d_in[0];
    const float* W_ih0 = (const float*)d_in[1];
    const float* W_hh0 = (const float*)d_in[2];
    const float* b_ih0 = (const float*)d_in[3];
    const float* b_hh0 = (const float*)d_in[4];
    const float* W_ih1 = (const float*)d_in[5];
    const float* W_hh1 = (const float*)d_in[6];
    const float* b_ih1 = (const float*)d_in[7];
    const float* b_hh1 = (const float*)d_in[8];
    const float* W_ih2 = (const float*)d_in[9];
    const float* W_hh2 = (const float*)d_in[10];
    const float* b_ih2 = (const float*)d_in[11];
    const float* b_hh2 = (const float*)d_in[12];
    const float* fc_w  = (const float*)d_in[13];
    const float* fc_b  = (const float*)d_in[14];

    float *pre, *h, *part;
    __nv_bfloat16 *Whi, *Wlo;
    cudaGetSymbolAddress((void**)&pre,  g_pre);
    cudaGetSymbolAddress((void**)&h,    g_h);
    cudaGetSymbolAddress((void**)&part, g_part);
    cudaGetSymbolAddress((void**)&Whi,  g_Whi);
    cudaGetSymbolAddress((void**)&Wlo,  g_Wlo);

    cudaFuncSetAttribute(rnn_scan, cudaFuncAttributeMaxDynamicSharedMemorySize, SCAN_SMEM);
    cudaFuncSetAttribute(gemm0_mma, cudaFuncAttributeMaxDynamicSharedMemorySize, GEMM_SMEM);

    // Layer 0: W split-convert, fused-cvt HMMA GEMM (K-split), reduce, scan
    cvt_split4<<<(H * (KPAD / 4) + 255) / 256, 256>>>(W_ih0, Whi, Wlo, H, DIN);
    gemm0_mma<<<dim3(KSPLIT, M_TOT / 128), 512, GEMM_SMEM>>>(x, Whi, Wlo, part);
    reduce_bias<<<(M_TOT * H + 255) / 256, 256>>>(part, b_ih0, b_hh0, pre);
    rnn_scan<<<B, SCAN_THREADS, SCAN_SMEM>>>(pre, W_hh0, h);

    dim3 gg((H + 63) / 64, M_TOT / 64);   // (4, 32)

    // Layer 1
    gemm_abt_bias<<<gg, 256>>>(h, W_ih1, b_ih1, b_hh1, pre, M_TOT, H, H);
    rnn_scan<<<B, SCAN_THREADS, SCAN_SMEM>>>(pre, W_hh1, h);

    // Layer 2
    gemm_abt_bias<<<gg, 256>>>(h, W_ih2, b_ih2, b_hh2, pre, M_TOT, H, H);
    rnn_scan<<<B, SCAN_THREADS, SCAN_SMEM>>>(pre, W_hh2, h);

    fc_kernel<<<1, 64>>>(h, fc_w, fc_b, (float*)d_out);
}